// round 8
// baseline (speedup 1.0000x reference)
#include <cuda_runtime.h>
#include <cstddef>

#define BATCH    256
#define DATA_DIM 8192
#define NNZ      256
#define QK       64
#define EMB      63
#define NSUB     8
#define WTS      68    // stride for W transpose in precompute shared
#define ITHREADS 512

typedef unsigned long long u64;

// Precomputed per-row projections of the embedding table (row 0 = padding row).
__device__ float4 g_Q0T[(DATA_DIM + 1) * 16];
__device__ float4 g_K0T[(DATA_DIM + 1) * 16];

// packed f32x2 FMA: acc = a*b + acc
__device__ __forceinline__ void fma2(u64& acc, u64 a, u64 b) {
    asm("fma.rn.f32x2 %0, %1, %2, %0;" : "+l"(acc) : "l"(a), "l"(b));
}
__device__ __forceinline__ float hsum2(u64 a) {
    return __uint_as_float((unsigned)a) + __uint_as_float((unsigned)(a >> 32));
}
__device__ __forceinline__ u64 pack2(float lo, float hi) {
    u64 r;
    asm("mov.b64 %0, {%1, %2};" : "=l"(r) : "f"(lo), "f"(hi));
    return r;
}

// ---------------------------------------------------------------------------
// Kernel P: 257 blocks x 32 table rows. W transposed to shared once per block,
// one barrier, then 2 groups of 16 rows computed barrier-free.
// Q0T[p][d] = bq[d] + sum_e embed[p][e] * Wq[d][e+1]   (same for K)
// ---------------------------------------------------------------------------
__global__ void __launch_bounds__(256)
precompute_kernel(const float* __restrict__ embed,
                  const float* __restrict__ Wq,
                  const float* __restrict__ bq,
                  const float* __restrict__ Wk,
                  const float* __restrict__ bk) {
    __shared__ __align__(16) float WqT[64 * WTS];
    __shared__ __align__(16) float WkT[64 * WTS];
    __shared__ __align__(16) float es[32][64];

    const int tid = threadIdx.x;
    for (int i = tid; i < 4096; i += 256) {
        int d = i >> 6, e = i & 63;
        WqT[e * WTS + d] = Wq[i];
        WkT[e * WTS + d] = Wk[i];
    }
    const int p0 = blockIdx.x * 32;
    for (int i = tid; i < 32 * 63; i += 256) {
        int r = i / 63, e = i - r * 63;
        int p = p0 + r;
        es[r][e] = (p <= DATA_DIM) ? embed[(size_t)p * EMB + e] : 0.0f;
    }
    __syncthreads();

    const int rl = tid >> 4, d4 = tid & 15;
    const float4 bq4 = __ldg(reinterpret_cast<const float4*>(bq) + d4);
    const float4 bk4 = __ldg(reinterpret_cast<const float4*>(bk) + d4);
#pragma unroll
    for (int grp = 0; grp < 2; ++grp) {
        const int r = grp * 16 + rl;
        const int p = p0 + r;
        if (p <= DATA_DIM) {
            float4 aq = bq4, ak = bk4;
#pragma unroll 9
            for (int e = 0; e < EMB; ++e) {
                float ev = es[r][e];
                float4 wq = *reinterpret_cast<const float4*>(&WqT[(e + 1) * WTS + 4 * d4]);
                float4 wk = *reinterpret_cast<const float4*>(&WkT[(e + 1) * WTS + 4 * d4]);
                aq.x += ev * wq.x; aq.y += ev * wq.y; aq.z += ev * wq.z; aq.w += ev * wq.w;
                ak.x += ev * wk.x; ak.y += ev * wk.y; ak.z += ev * wk.z; ak.w += ev * wk.w;
            }
            g_Q0T[(size_t)p * 16 + d4] = aq;
            g_K0T[(size_t)p * 16 + d4] = ak;
        }
    }
}

// ---------------------------------------------------------------------------
// Kernel C: 512 threads/block. Each i owned by 2 threads (halves of the q0
// row); m-matvec split into 8 chunks of 32. ALL matrix data register-resident;
// per-eval shared traffic is vectors only. 2 blocks/SM, 1 wave.
// ---------------------------------------------------------------------------
__global__ void __launch_bounds__(ITHREADS, 2)
integrate_kernel(const float* __restrict__ t,
                 const float* __restrict__ x,
                 const float* __restrict__ Wq,
                 const float* __restrict__ Wk,
                 float* __restrict__ out) {
    __shared__ __align__(16) float wsh[NNZ];
    __shared__ __align__(16) float ssh[QK];
    __shared__ __align__(16) float mpart[ITHREADS];
    __shared__ __align__(16) float qpart[ITHREADS];
    __shared__ __align__(16) float red1[8];    // per-h1-warp w^2 partials
    __shared__ __align__(16) float red2[8];    // per-h0-warp w*f partials
    __shared__ __align__(16) float c1p[2];
    __shared__ __align__(16) float val[NNZ];
    __shared__ int idx[NNZ];
    __shared__ int wscan[16];

    const int tid  = threadIdx.x;
    const int b    = blockIdx.x;
    const int lane = tid & 31;
    const int wid  = tid >> 5;
    const int i    = tid & 255;    // owned position
    const int h    = tid >> 8;     // half (0/1) of the q0 row

    // ---- Phase 0: zero this block's two output rows ----
    {
        float4 z = make_float4(0.f, 0.f, 0.f, 0.f);
        float4* o4 = reinterpret_cast<float4*>(out);
        for (int k = tid; k < 2048; k += ITHREADS) {
            o4[(size_t)b * 2048 + k] = z;
            o4[(size_t)(BATCH + b) * 2048 + k] = z;
        }
    }

    // ---- Phase 1: scan + order-preserving compaction (16 elems/thread) ----
    float xr[16];
    {
        const float4* xrow4 = reinterpret_cast<const float4*>(x + (size_t)b * DATA_DIM) + tid * 4;
#pragma unroll
        for (int j = 0; j < 4; ++j) {
            float4 f = xrow4[j];
            xr[4 * j + 0] = f.x; xr[4 * j + 1] = f.y;
            xr[4 * j + 2] = f.z; xr[4 * j + 3] = f.w;
        }
    }
    if (tid < NNZ) { val[tid] = 0.0f; idx[tid] = 0; }

    int cnt = 0;
#pragma unroll
    for (int j = 0; j < 16; ++j) cnt += (xr[j] != 0.0f) ? 1 : 0;
    int inc = cnt;
#pragma unroll
    for (int o = 1; o < 32; o <<= 1) {
        int u = __shfl_up_sync(0xffffffffu, inc, o);
        if (lane >= o) inc += u;
    }
    if (lane == 31) wscan[wid] = inc;
    __syncthreads();
    int woff = 0;
#pragma unroll
    for (int wdx = 0; wdx < 16; ++wdx) woff += (wdx < wid) ? wscan[wdx] : 0;
    int o = woff + inc - cnt;
#pragma unroll
    for (int j = 0; j < 16; ++j) {
        float v = xr[j];
        if (v != 0.0f && o < NNZ) {
            val[o] = v;
            idx[o] = tid * 16 + j;
            ++o;
        }
    }
    __syncthreads();

    // ---- Phase 2: all-register gathers ----
    const int p     = idx[i] + 1;
    const float myv = val[i];

    if (h == 0) out[(size_t)b * DATA_DIM + (p - 1)] = myv;   // t=0 plane

    // my q0 HALF-row: d in [32h, 32h+32) -> 16 packed regs
    u64 q0u[16];
    {
        const ulonglong2* qrow =
            reinterpret_cast<const ulonglong2*>(g_Q0T + (size_t)p * 16) + h * 4;
#pragma unroll
        for (int m = 0; m < 8; ++m) {
            ulonglong2 v = qrow[m];
            q0u[2 * m] = v.x; q0u[2 * m + 1] = v.y;
        }
    }

    // my k0 chunk: K0[p_j][dd] for j in [32cc, 32cc+32) -> 16 packed regs
    const int dd = tid & 63, cc = tid >> 6;   // cc in 0..7
    u64 k0u[16];
    {
        const float* k0g = reinterpret_cast<const float*>(g_K0T);
        const int jb = cc * 32;
#pragma unroll
        for (int m = 0; m < 16; ++m) {
            int pa = idx[jb + 2 * m] + 1;
            int pb = idx[jb + 2 * m + 1] + 1;
            float fa = __ldg(k0g + (size_t)pa * 64 + dd);
            float fb = __ldg(k0g + (size_t)pb * 64 + dd);
            k0u[m] = pack2(fa, fb);
        }
    }

    float avd = 0.0f, bvd = 0.0f;
    if (tid < QK) { avd = Wq[tid * 64]; bvd = Wk[tid * 64]; }

    const float dt = (t[1] - t[0]) * (1.0f / (float)NSUB);
    const ulonglong2* wvp = reinterpret_cast<const ulonglong2*>(wsh + cc * 32);
    const ulonglong2* svp = reinterpret_cast<const ulonglong2*>(ssh + h * 32);

    // stage: h0 publishes w; h1 warps compute the w^2 tree in parallel.
    // caller must __syncthreads() after.
    auto stage = [&](float w) {
        if (h == 0) {
            wsh[i] = w;
        } else {
            float w2 = w * w;
#pragma unroll
            for (int o2 = 16; o2 > 0; o2 >>= 1) w2 += __shfl_xor_sync(0xffffffffu, w2, o2);
            if (lane == 0) red1[wid - 8] = w2;
        }
    };

    // dxdt(w) = w*(f - g);  s = S2*b + K0^T w;  f_i = (c1*w_i + q0_i.s)/8;
    // c1 = a.s;  g = sum_j w_j f_j.  precondition: stage(w) + sync done.
    auto dxdt = [&](float w) -> float {
        // m partial over my 32-j chunk (pure register FMA, broadcast w reads)
        u64 a0 = 0ull, a1 = 0ull;
#pragma unroll
        for (int m = 0; m < 8; ++m) {
            ulonglong2 wv = wvp[m];
            fma2(a0, k0u[2 * m], wv.x);
            fma2(a1, k0u[2 * m + 1], wv.y);
        }
        mpart[tid] = hsum2(a0) + hsum2(a1);
        __syncthreads();                                   // BAR A

        if (tid < QK) {
            float4 r1a = *reinterpret_cast<const float4*>(&red1[0]);
            float4 r1b = *reinterpret_cast<const float4*>(&red1[4]);
            float S2 = (r1a.x + r1a.y) + (r1a.z + r1a.w) + (r1b.x + r1b.y) + (r1b.z + r1b.w);
            float m = ((mpart[tid]       + mpart[tid + 64]) + (mpart[tid + 128] + mpart[tid + 192]))
                    + ((mpart[tid + 256] + mpart[tid + 320]) + (mpart[tid + 384] + mpart[tid + 448]));
            float sv = S2 * bvd + m;
            ssh[tid] = sv;
            float cp = avd * sv;
#pragma unroll
            for (int o2 = 16; o2 > 0; o2 >>= 1) cp += __shfl_xor_sync(0xffffffffu, cp, o2);
            if (lane == 0) c1p[wid] = cp;                  // wid = 0 or 1
        }
        __syncthreads();                                   // BAR B

        // q partial over my 32-d half (register FMA, broadcast s reads)
        u64 b0 = 0ull, b1 = 0ull;
#pragma unroll
        for (int m = 0; m < 8; ++m) {
            ulonglong2 sv = svp[m];
            fma2(b0, q0u[2 * m], sv.x);
            fma2(b1, q0u[2 * m + 1], sv.y);
        }
        qpart[tid] = hsum2(b0) + hsum2(b1);
        __syncthreads();                                   // BAR C

        float qdot = qpart[i] + qpart[i + 256];
        float c1 = c1p[0] + c1p[1];
        float f  = (c1 * w + qdot) * 0.125f;               // 1/sqrt(64)

        if (h == 0) {
            float wf = w * f;
#pragma unroll
            for (int o2 = 16; o2 > 0; o2 >>= 1) wf += __shfl_xor_sync(0xffffffffu, wf, o2);
            if (lane == 0) red2[wid] = wf;
        }
        __syncthreads();                                   // BAR D
        float4 r2a = *reinterpret_cast<const float4*>(&red2[0]);
        float4 r2b = *reinterpret_cast<const float4*>(&red2[4]);
        float g = (r2a.x + r2a.y) + (r2a.z + r2a.w) + (r2b.x + r2b.y) + (r2b.z + r2b.w);

        return w * (f - g);
    };

    // Both owners of i carry identical vcur (identical arithmetic).
    float vcur = myv;
    stage(vcur);
    __syncthreads();

    // ---- Phase 3: 8 RK4 substeps over [t0, t1] ----
    for (int stp = 0; stp < NSUB; ++stp) {
        float k1 = dxdt(vcur);
        float w2s = vcur + 0.5f * dt * k1;
        stage(w2s); __syncthreads();
        float k2 = dxdt(w2s);
        float w3s = vcur + 0.5f * dt * k2;
        stage(w3s); __syncthreads();
        float k3 = dxdt(w3s);
        float w4s = vcur + dt * k3;
        stage(w4s); __syncthreads();
        float k4 = dxdt(w4s);
        vcur += dt * (1.0f / 6.0f) * (k1 + 2.0f * k2 + 2.0f * k3 + k4);
        stage(vcur); __syncthreads();
    }

    // t=1 plane
    if (h == 0) out[(size_t)BATCH * DATA_DIM + (size_t)b * DATA_DIM + (p - 1)] = vcur;
}

// ---------------------------------------------------------------------------
// kernel_launch
// ---------------------------------------------------------------------------
extern "C" void kernel_launch(void* const* d_in, const int* in_sizes, int n_in,
                              void* d_out, int out_size) {
    const float* t     = (const float*)d_in[0];
    const float* x     = (const float*)d_in[1];
    const float* embed = (const float*)d_in[2];
    const float* Wq    = (const float*)d_in[3];
    const float* bq    = (const float*)d_in[4];
    const float* Wk    = (const float*)d_in[5];
    const float* bk    = (const float*)d_in[6];
    float* out = (float*)d_out;

    precompute_kernel<<<(DATA_DIM + 1 + 31) / 32, 256>>>(embed, Wq, bq, Wk, bk);
    integrate_kernel<<<BATCH, ITHREADS>>>(t, x, Wq, Wk, out);
}